// round 7
// baseline (speedup 1.0000x reference)
#include <cuda_runtime.h>
#include <cstdint>

// Problem dims
#define NBAGS 512
#define MSENT 8
#define TLEN  64
#define IND   360
#define HD    230
#define G3    690      // 3*HD
#define H2    460      // 2*HD
#define OUTD  53
#define BALL  4096     // NBAGS*MSENT
#define ROWSALL 262144 // BALL*TLEN

// ---------------- scratch (static device globals; allocation-free) ----------------
__device__ float g_xg_f[(size_t)ROWSALL * G3];  // input gates, forward  (~689 MB)
__device__ float g_xg_r[(size_t)ROWSALL * G3];  // input gates, reverse  (~689 MB)
__device__ float g_hcat[(size_t)ROWSALL * H2];  // [b][t][hf|hr]         (~460 MB)
__device__ float g_sw[ROWSALL];                 // word scores
__device__ float g_wv[(size_t)BALL * H2];       // word vectors
__device__ float g_ss[BALL];                    // sentence scores
__device__ float g_sv[(size_t)NBAGS * H2];      // sentence vectors

// =====================================================================
// K1: input projection  C[bt][g] = sum_i bag[bt][i]*W_ih[g][i] + b_ih[g]
// BM=128, BN=64, BK=8, 256 thr, 8x4 microkernel. grid.z = dir.
// =====================================================================
__global__ void __launch_bounds__(256) k_proj(const float* __restrict__ bag,
        const float* __restrict__ Wf, const float* __restrict__ bf,
        const float* __restrict__ Wr, const float* __restrict__ br)
{
    __shared__ float As[8][128];
    __shared__ float Bs[8][64];
    const int dir = blockIdx.z;
    const float* W    = dir ? Wr : Wf;
    const float* bias = dir ? br : bf;
    float* C = dir ? g_xg_r : g_xg_f;

    const int m0 = blockIdx.y * 128;
    const int g0 = blockIdx.x * 64;
    const int tid = threadIdx.x;
    const int tx = tid & 15;   // N: 16 x 4 = 64
    const int ty = tid >> 4;   // M: 16 x 8 = 128

    float acc[8][4] = {};

    const int arow = tid >> 1;
    const int ak   = (tid & 1) * 4;
    const int bidx = tid * 2;
    const int bg   = bidx >> 3;
    const int bk   = bidx & 7;

    for (int k0 = 0; k0 < IND; k0 += 8) {
        float4 av = *(const float4*)(bag + (size_t)(m0 + arow) * IND + k0 + ak);
        float2 bv = make_float2(0.f, 0.f);
        int gg = g0 + bg;
        if (gg < G3) bv = *(const float2*)(W + (size_t)gg * IND + k0 + bk);
        __syncthreads();
        As[ak + 0][arow] = av.x; As[ak + 1][arow] = av.y;
        As[ak + 2][arow] = av.z; As[ak + 3][arow] = av.w;
        Bs[bk + 0][bg] = bv.x;   Bs[bk + 1][bg] = bv.y;
        __syncthreads();
        #pragma unroll
        for (int k = 0; k < 8; k++) {
            float a[8], b4[4];
            *(float4*)(a)     = *(const float4*)&As[k][ty * 8];
            *(float4*)(a + 4) = *(const float4*)&As[k][ty * 8 + 4];
            *(float4*)(b4)    = *(const float4*)&Bs[k][tx * 4];
            #pragma unroll
            for (int i = 0; i < 8; i++)
                #pragma unroll
                for (int j = 0; j < 4; j++)
                    acc[i][j] += a[i] * b4[j];
        }
    }
    #pragma unroll
    for (int i = 0; i < 8; i++) {
        size_t row = (size_t)m0 + ty * 8 + i;
        #pragma unroll
        for (int j = 0; j < 4; j++) {
            int g = g0 + tx * 4 + j;
            if (g < G3) C[row * G3 + g] = acc[i][j] + bias[g];
        }
    }
}

// =====================================================================
// K2: GRU. One CTA owns 32 batch rows for one direction; full T loop
// with h resident in smem. Per step: hg = h @ W_hh^T (+b_hh) computed in
// 11 g-tiles of 64 with W staged to smem, then elementwise gates.
// smem: h_s[32][231] + ws[64][231] + hg[32][690] = 177,024 B
// =====================================================================
__global__ void __launch_bounds__(256) k_gru(const float* __restrict__ Whhf,
        const float* __restrict__ bhhf, const float* __restrict__ Whhr,
        const float* __restrict__ bhhr)
{
    extern __shared__ float sm[];
    float* h_s = sm;                       // 32*231
    float* ws  = sm + 32 * 231;            // 64*231
    float* hg  = sm + 32 * 231 + 64 * 231; // 32*690

    const int bx  = blockIdx.x;
    const int dir = bx >> 7;          // 128 CTAs per dir
    const int rb  = (bx & 127) * 32;
    const float* Whh = dir ? Whhr : Whhf;
    const float* bhh = dir ? bhhr : bhhf;
    const float* xg  = dir ? g_xg_r : g_xg_f;

    const int tid = threadIdx.x;
    const int gx = tid & 63;
    const int ry = tid >> 6;

    for (int i = tid; i < 32 * 231; i += 256) h_s[i] = 0.f;
    __syncthreads();

    for (int ti = 0; ti < TLEN; ti++) {
        const int t = dir ? (TLEN - 1 - ti) : ti;
        // hg = h @ Whh^T + bhh, tiled over g
        for (int tile = 0; tile < 11; tile++) {
            const int g0 = tile * 64;
            __syncthreads();   // prev compute & gate done before ws overwrite
            for (int idx = tid; idx < 64 * HD; idx += 256) {
                int gg = idx / HD;
                int kk = idx - gg * HD;
                int g = g0 + gg;
                ws[gg * 231 + kk] = (g < G3) ? Whh[(size_t)g * HD + kk] : 0.f;
            }
            __syncthreads();
            const int g = g0 + gx;
            float acc[8] = {};
            #pragma unroll 2
            for (int k = 0; k < HD; k++) {
                float w = ws[gx * 231 + k];
                #pragma unroll
                for (int i = 0; i < 8; i++)
                    acc[i] += w * h_s[(ry * 8 + i) * 231 + k];
            }
            if (g < G3) {
                float bb = bhh[g];
                #pragma unroll
                for (int i = 0; i < 8; i++)
                    hg[(ry * 8 + i) * G3 + g] = acc[i] + bb;
            }
        }
        __syncthreads();
        // gates + state update + output
        for (int e = tid; e < 32 * HD; e += 256) {
            int r_ = e / HD;
            int j  = e - r_ * HD;
            size_t xb = ((size_t)(rb + r_) * TLEN + t) * G3;
            float xr = xg[xb + j];
            float xz = xg[xb + HD + j];
            float xn = xg[xb + 2 * HD + j];
            float hgr = hg[r_ * G3 + j];
            float hgz = hg[r_ * G3 + HD + j];
            float hgn = hg[r_ * G3 + 2 * HD + j];
            float rr = 1.f / (1.f + __expf(-(xr + hgr)));
            float zz = 1.f / (1.f + __expf(-(xz + hgz)));
            float nn = tanhf(xn + rr * hgn);
            float hold = h_s[r_ * 231 + j];
            float hn = (1.f - zz) * nn + zz * hold;
            h_s[r_ * 231 + j] = hn;
            g_hcat[((size_t)(rb + r_) * TLEN + t) * H2 + dir * HD + j] = hn;
        }
    }
}

// =====================================================================
// K3: attention score  s[row] = p . tanh(X[row] @ W + b)
// 32 rows/CTA, W staged in 460x64 smem tiles. Deterministic tree reduce.
// smem: xs[32*460] + Wt[460*65] + red[64*32] = 186,672 B
// =====================================================================
__global__ void __launch_bounds__(256) k_score(const float* __restrict__ X,
        const float* __restrict__ W, const float* __restrict__ b,
        const float* __restrict__ p, float* __restrict__ s)
{
    extern __shared__ float sm[];
    float* xs  = sm;                 // 32*460
    float* Wt  = sm + 32 * H2;       // 460*65
    float* red = Wt + H2 * 65;       // 64*32

    const int r0 = blockIdx.x * 32;
    const int tid = threadIdx.x;
    const int jx = tid & 63;
    const int ry = tid >> 6;

    for (int idx = tid; idx < 32 * H2; idx += 256)
        xs[idx] = X[(size_t)r0 * H2 + idx];

    float sacc[8] = {};
    for (int j0 = 0; j0 < H2; j0 += 64) {
        __syncthreads();
        for (int idx = tid; idx < H2 * 64; idx += 256) {
            int i  = idx >> 6;
            int jj = idx & 63;
            int j = j0 + jj;
            Wt[i * 65 + jj] = (j < H2) ? W[(size_t)i * H2 + j] : 0.f;
        }
        __syncthreads();
        int j = j0 + jx;
        if (j < H2) {
            float facc[8] = {};
            for (int i = 0; i < H2; i++) {
                float w = Wt[i * 65 + jx];
                #pragma unroll
                for (int r = 0; r < 8; r++)
                    facc[r] += w * xs[(ry * 8 + r) * H2 + i];
            }
            float pj = p[j], bj = b[j];
            #pragma unroll
            for (int r = 0; r < 8; r++)
                sacc[r] += pj * tanhf(facc[r] + bj);
        }
    }
    __syncthreads();
    #pragma unroll
    for (int r = 0; r < 8; r++)
        red[jx * 32 + ry * 8 + r] = sacc[r];
    __syncthreads();
    if (tid < 32) {
        float v = 0.f;
        for (int q = 0; q < 64; q++) v += red[q * 32 + tid];
        s[r0 + tid] = v;
    }
}

// =====================================================================
// K4: softmax over L within a group + weighted sum -> V[group][460]
// =====================================================================
__global__ void k_attnsum(const float* __restrict__ s, const float* __restrict__ X,
                          float* __restrict__ V, int L)
{
    __shared__ float sv[64];
    __shared__ float alpha[64];
    const int b = blockIdx.x;
    const int tid = threadIdx.x;
    if (tid < L) sv[tid] = s[b * L + tid];
    __syncthreads();
    float m = -1e30f;
    for (int l = 0; l < L; l++) m = fmaxf(m, sv[l]);
    float den = 0.f;
    for (int l = 0; l < L; l++) den += __expf(sv[l] - m);
    if (tid < L) alpha[tid] = __expf(sv[tid] - m) / den;
    __syncthreads();
    for (int j = tid; j < H2; j += blockDim.x) {
        float acc = 0.f;
        for (int l = 0; l < L; l++)
            acc += alpha[l] * X[((size_t)b * L + l) * H2 + j];
        V[(size_t)b * H2 + j] = acc;
    }
}

// =====================================================================
// K5: FC on sentence vectors + scatter into (DOCS,ENT,ENT,OUT)
// =====================================================================
__global__ void k_fc_scatter(const float* __restrict__ fcW, const float* __restrict__ fcb,
                             const int* __restrict__ pairs, float* __restrict__ out)
{
    __shared__ float sv[H2];
    const int r = blockIdx.x;
    const int tid = threadIdx.x;
    for (int j = tid; j < H2; j += blockDim.x) sv[j] = g_sv[(size_t)r * H2 + j];
    __syncthreads();
    if (tid < OUTD) {
        float acc = fcb[tid];
        for (int j = 0; j < H2; j++) acc += sv[j] * fcW[(size_t)tid * H2 + j];
        int p0 = pairs[r * 3], p1 = pairs[r * 3 + 1], p2 = pairs[r * 3 + 2];
        out[((size_t)(p0 * 64 + p1 * 8 + p2)) * OUTD + tid] = acc;
    }
}

__global__ void k_zero(float* __restrict__ out, int n)
{
    int i = blockIdx.x * blockDim.x + threadIdx.x;
    if (i < n) out[i] = 0.f;
}

// =====================================================================
extern "C" void kernel_launch(void* const* d_in, const int* in_sizes, int n_in,
                              void* d_out, int out_size)
{
    const float* bag   = (const float*)d_in[0];
    const float* Wihf  = (const float*)d_in[1];
    const float* Whhf  = (const float*)d_in[2];
    const float* bihf  = (const float*)d_in[3];
    const float* bhhf  = (const float*)d_in[4];
    const float* Wihr  = (const float*)d_in[5];
    const float* Whhr  = (const float*)d_in[6];
    const float* bihr  = (const float*)d_in[7];
    const float* bhhr  = (const float*)d_in[8];
    const float* Wword = (const float*)d_in[9];
    const float* bword = (const float*)d_in[10];
    const float* pword = (const float*)d_in[11];
    const float* Wsent = (const float*)d_in[12];
    const float* bsent = (const float*)d_in[13];
    const float* psent = (const float*)d_in[14];
    const float* fcW   = (const float*)d_in[15];
    const float* fcb   = (const float*)d_in[16];
    const int*   pairs = (const int*)d_in[17];
    float* out = (float*)d_out;

    // device-symbol addresses for the reusable kernels
    void *p_hcat, *p_sw, *p_wv, *p_ss, *p_sv;
    cudaGetSymbolAddress(&p_hcat, g_hcat);
    cudaGetSymbolAddress(&p_sw,   g_sw);
    cudaGetSymbolAddress(&p_wv,   g_wv);
    cudaGetSymbolAddress(&p_ss,   g_ss);
    cudaGetSymbolAddress(&p_sv,   g_sv);

    const size_t smem_gru   = (size_t)(32 * 231 + 64 * 231 + 32 * 690) * sizeof(float); // 177,024
    const size_t smem_score = (size_t)(32 * H2 + H2 * 65 + 64 * 32) * sizeof(float);    // 186,672
    cudaFuncSetAttribute(k_gru,   cudaFuncAttributeMaxDynamicSharedMemorySize, (int)smem_gru);
    cudaFuncSetAttribute(k_score, cudaFuncAttributeMaxDynamicSharedMemorySize, (int)smem_score);

    // 1) zero output (poisoned by harness)
    k_zero<<<(out_size + 255) / 256, 256>>>(out, out_size);

    // 2) input projections for both directions
    dim3 gproj((G3 + 63) / 64, ROWSALL / 128, 2);
    k_proj<<<gproj, 256>>>(bag, Wihf, bihf, Wihr, bihr);

    // 3) bidirectional GRU (128 CTAs per dir)
    k_gru<<<256, 256, smem_gru>>>(Whhf, bhhf, Whhr, bhhr);

    // 4) word attention
    k_score<<<ROWSALL / 32, 256, smem_score>>>((const float*)p_hcat, Wword, bword, pword, (float*)p_sw);
    k_attnsum<<<BALL, 256>>>((const float*)p_sw, (const float*)p_hcat, (float*)p_wv, TLEN);

    // 5) sentence attention
    k_score<<<BALL / 32, 256, smem_score>>>((const float*)p_wv, Wsent, bsent, psent, (float*)p_ss);
    k_attnsum<<<NBAGS, 256>>>((const float*)p_ss, (const float*)p_wv, (float*)p_sv, MSENT);

    // 6) FC + scatter
    k_fc_scatter<<<NBAGS, 64>>>(fcW, fcb, pairs, out);
}

// round 9
// speedup vs baseline: 1.2864x; 1.2864x over previous
#include <cuda_runtime.h>
#include <cuda_bf16.h>
#include <cstdint>

// Problem dims
#define NBAGS 512
#define MSENT 8
#define TLEN  64
#define IND   360
#define HD    230
#define G3    690
#define H2    460
#define OUTD  53
#define BALL  4096
#define ROWSALL 262144

#define KATOMS 24            // 384 / 16
#define MATOMS (ROWSALL/16)  // 16384
#define NATOMS 96            // 768 / 8

// ---------------- scratch (static device globals) ----------------
__device__ float g_xg_f[(size_t)ROWSALL * G3];
__device__ float g_xg_r[(size_t)ROWSALL * G3];
__device__ float g_hcat[(size_t)ROWSALL * H2];
// fragment-packed operands: A atom = 16x16 bf16 (256 elems, [lane][4 regs]),
// B atom = 16x8 bf16 (128 elems, [lane][2 regs])
__device__ __nv_bfloat16 g_Ahi[(size_t)MATOMS * KATOMS * 256];
__device__ __nv_bfloat16 g_Alo[(size_t)MATOMS * KATOMS * 256];
__device__ __nv_bfloat16 g_Bhi[(size_t)2 * NATOMS * KATOMS * 128];
__device__ __nv_bfloat16 g_Blo[(size_t)2 * NATOMS * KATOMS * 128];
__device__ float g_sw[ROWSALL];
__device__ float g_wv[(size_t)BALL * H2];
__device__ float g_ss[BALL];
__device__ float g_sv[(size_t)NBAGS * H2];

// ---------------- helpers ----------------
__device__ __forceinline__ unsigned pack_split(float x, float y, unsigned& lo)
{
    __nv_bfloat16 hx = __float2bfloat16(x);
    __nv_bfloat16 hy = __float2bfloat16(y);
    __nv_bfloat16 lx = __float2bfloat16(x - __bfloat162float(hx));
    __nv_bfloat16 ly = __float2bfloat16(y - __bfloat162float(hy));
    __nv_bfloat162 ph; ph.x = hx; ph.y = hy;
    __nv_bfloat162 pl; pl.x = lx; pl.y = ly;
    lo = *(unsigned*)&pl;
    return *(unsigned*)&ph;
}

#define MMA16816(c, a, b) \
    asm volatile("mma.sync.aligned.m16n8k16.row.col.f32.bf16.bf16.f32 " \
        "{%0,%1,%2,%3}, {%4,%5,%6,%7}, {%8,%9}, {%0,%1,%2,%3};" \
        : "+f"((c)[0]), "+f"((c)[1]), "+f"((c)[2]), "+f"((c)[3]) \
        : "r"((a).x), "r"((a).y), "r"((a).z), "r"((a).w), "r"((b).x), "r"((b).y))

// =====================================================================
// pack A (bag rows) into mma fragment order, split bf16 hi/lo.
// atom (mi,ki): lane l (gid=l>>2, tig=l&3) holds:
//   reg0: (row mi*16+gid,   k ki*16+tig*2, +1)
//   reg1: (row mi*16+gid+8, same k)
//   reg2: (row mi*16+gid,   k +8, +9)
//   reg3: (row mi*16+gid+8, k +8, +9)
// =====================================================================
__global__ void __launch_bounds__(256) k_pack_a(const float* __restrict__ bag)
{
    const int mi  = blockIdx.x;
    const int wid = threadIdx.x >> 5, lane = threadIdx.x & 31;
    const int gid = lane >> 2, tig = lane & 3;
    const size_t r0 = (size_t)mi * 16 + gid;
    const size_t r1 = r0 + 8;
    for (int ki = wid; ki < KATOMS; ki += 8) {
        const int kb = ki * 16 + tig * 2;
        float2 v0 = (kb     < IND) ? *(const float2*)(bag + r0 * IND + kb)     : make_float2(0.f, 0.f);
        float2 v1 = (kb     < IND) ? *(const float2*)(bag + r1 * IND + kb)     : make_float2(0.f, 0.f);
        float2 v2 = (kb + 8 < IND) ? *(const float2*)(bag + r0 * IND + kb + 8) : make_float2(0.f, 0.f);
        float2 v3 = (kb + 8 < IND) ? *(const float2*)(bag + r1 * IND + kb + 8) : make_float2(0.f, 0.f);
        uint4 hi, lo;
        hi.x = pack_split(v0.x, v0.y, lo.x);
        hi.y = pack_split(v1.x, v1.y, lo.y);
        hi.z = pack_split(v2.x, v2.y, lo.z);
        hi.w = pack_split(v3.x, v3.y, lo.w);
        size_t off = ((size_t)mi * KATOMS + ki) * 256 + lane * 8;
        *(uint4*)(g_Ahi + off) = hi;
        *(uint4*)(g_Alo + off) = lo;
    }
}

// =====================================================================
// pack W (both dirs) into B fragment order (col-major k x n), split hi/lo.
// atom (ni,ki): lane l: col n = ni*8+gid; reg0: k=ki*16+tig*2,+1; reg1: k+8,+9
// =====================================================================
__global__ void __launch_bounds__(128) k_pack_b(const float* __restrict__ Wf, const float* __restrict__ Wr)
{
    const int b = blockIdx.x;            // 0..2*NATOMS-1
    const int dir = b / NATOMS, ni = b - dir * NATOMS;
    const float* W = dir ? Wr : Wf;
    const int wid = threadIdx.x >> 5, lane = threadIdx.x & 31;
    const int gid = lane >> 2, tig = lane & 3;
    const int n = ni * 8 + gid;
    const bool nok = (n < G3);
    for (int ki = wid; ki < KATOMS; ki += 4) {
        const int kb = ki * 16 + tig * 2;
        float2 v0 = (nok && kb     < IND) ? *(const float2*)(W + (size_t)n * IND + kb)     : make_float2(0.f, 0.f);
        float2 v1 = (nok && kb + 8 < IND) ? *(const float2*)(W + (size_t)n * IND + kb + 8) : make_float2(0.f, 0.f);
        uint2 hi, lo;
        hi.x = pack_split(v0.x, v0.y, lo.x);
        hi.y = pack_split(v1.x, v1.y, lo.y);
        size_t off = ((size_t)b * KATOMS + ki) * 128 + lane * 4;
        *(uint2*)(g_Bhi + off) = hi;
        *(uint2*)(g_Blo + off) = lo;
    }
}

// =====================================================================
// proj GEMM via mma.sync: C_dir[m][g] = sum_k A[m][k]*W_dir[g][k] + bias[g]
// grid (6 ntiles, 2048 mtiles, 2 dirs), 256 thr = 8 warps (2m x 4n),
// warp tile 64x32. Split-bf16: 3 MMAs per atom pair, fp32 accum in regs.
// =====================================================================
__global__ void __launch_bounds__(256) k_mma_proj(const float* __restrict__ bf_, const float* __restrict__ br_)
{
    const int tid = threadIdx.x, wid = tid >> 5, lane = tid & 31;
    const int wm = wid >> 2, wn = wid & 3;
    const int m0 = blockIdx.y * 128;
    const int n0 = blockIdx.x * 128;
    const int dir = blockIdx.z;

    const __nv_bfloat16* Bh = g_Bhi + (size_t)dir * NATOMS * KATOMS * 128;
    const __nv_bfloat16* Bl = g_Blo + (size_t)dir * NATOMS * KATOMS * 128;

    const int miG0 = (m0 >> 4) + wm * 4;
    const int niG0 = (n0 >> 3) + wn * 4;

    float acc[4][4][4] = {};

    for (int ki = 0; ki < KATOMS; ki++) {
        uint4 ah[4], al[4];
        uint2 bh[4], bl[4];
        #pragma unroll
        for (int mi = 0; mi < 4; mi++) {
            size_t off = ((size_t)(miG0 + mi) * KATOMS + ki) * 256 + lane * 8;
            ah[mi] = *(const uint4*)(g_Ahi + off);
            al[mi] = *(const uint4*)(g_Alo + off);
        }
        #pragma unroll
        for (int ni = 0; ni < 4; ni++) {
            size_t off = ((size_t)(niG0 + ni) * KATOMS + ki) * 128 + lane * 4;
            bh[ni] = *(const uint2*)(Bh + off);
            bl[ni] = *(const uint2*)(Bl + off);
        }
        #pragma unroll
        for (int mi = 0; mi < 4; mi++)
            #pragma unroll
            for (int ni = 0; ni < 4; ni++) {
                MMA16816(acc[mi][ni], ah[mi], bh[ni]);
                MMA16816(acc[mi][ni], ah[mi], bl[ni]);
                MMA16816(acc[mi][ni], al[mi], bh[ni]);
            }
    }

    // epilogue: c0,c1 -> (row gid, col tig*2/+1); c2,c3 -> (row gid+8)
    const float* bias = dir ? br_ : bf_;
    float* C = dir ? g_xg_r : g_xg_f;
    const int gid = lane >> 2, tig = lane & 3;
    #pragma unroll
    for (int mi = 0; mi < 4; mi++) {
        const size_t r0 = (size_t)m0 + wm * 64 + mi * 16 + gid;
        const size_t r1 = r0 + 8;
        #pragma unroll
        for (int ni = 0; ni < 4; ni++) {
            const int g = n0 + wn * 32 + ni * 8 + tig * 2;
            if (g < G3) {
                float2 bv = *(const float2*)(bias + g);
                float2 o0 = make_float2(acc[mi][ni][0] + bv.x, acc[mi][ni][1] + bv.y);
                float2 o1 = make_float2(acc[mi][ni][2] + bv.x, acc[mi][ni][3] + bv.y);
                *(float2*)(C + r0 * G3 + g) = o0;
                *(float2*)(C + r1 * G3 + g) = o1;
            }
        }
    }
}

// =====================================================================
// K2: GRU (float4-vectorized, padded stride 236)
// smem: h_s[32*236] + ws[64*236] + hg[32*690] = 178,944 B
// =====================================================================
#define HP 236
__global__ void __launch_bounds__(256) k_gru(const float* __restrict__ Whhf,
        const float* __restrict__ bhhf, const float* __restrict__ Whhr,
        const float* __restrict__ bhhr)
{
    extern __shared__ float sm[];
    float* h_s = sm;
    float* ws  = sm + 32 * HP;
    float* hg  = sm + 32 * HP + 64 * HP;

    const int bx  = blockIdx.x;
    const int dir = bx >> 7;
    const int rb  = (bx & 127) * 32;
    const float* Whh = dir ? Whhr : Whhf;
    const float* bhh = dir ? bhhr : bhhf;
    const float* xg  = dir ? g_xg_r : g_xg_f;

    const int tid = threadIdx.x;
    const int gx = tid & 63;
    const int ry = tid >> 6;

    for (int i = tid; i < 32 * HP; i += 256) h_s[i] = 0.f;
    __syncthreads();

    for (int ti = 0; ti < TLEN; ti++) {
        const int t = dir ? (TLEN - 1 - ti) : ti;
        for (int tile = 0; tile < 11; tile++) {
            const int g0 = tile * 64;
            __syncthreads();
            for (int idx = tid; idx < 64 * HP; idx += 256) {
                int gg = idx / HP;
                int kk = idx - gg * HP;
                int g = g0 + gg;
                ws[idx] = (g < G3 && kk < HD) ? Whh[(size_t)g * HD + kk] : 0.f;
            }
            __syncthreads();
            const int g = g0 + gx;
            float acc[8] = {};
            const float* wrow = ws + gx * HP;
            for (int k = 0; k < 232; k += 4) {
                float4 w4 = *(const float4*)(wrow + k);
                #pragma unroll
                for (int i = 0; i < 8; i++) {
                    float4 h4 = *(const float4*)(h_s + (ry * 8 + i) * HP + k);
                    acc[i] = fmaf(w4.x, h4.x, fmaf(w4.y, h4.y, fmaf(w4.z, h4.z, fmaf(w4.w, h4.w, acc[i]))));
                }
            }
            if (g < G3) {
                float bb = bhh[g];
                #pragma unroll
                for (int i = 0; i < 8; i++)
                    hg[(ry * 8 + i) * G3 + g] = acc[i] + bb;
            }
        }
        __syncthreads();
        for (int e = tid; e < 32 * HD; e += 256) {
            int r_ = e / HD;
            int j  = e - r_ * HD;
            size_t xb = ((size_t)(rb + r_) * TLEN + t) * G3;
            float xr = xg[xb + j];
            float xz = xg[xb + HD + j];
            float xn = xg[xb + 2 * HD + j];
            float hgr = hg[r_ * G3 + j];
            float hgz = hg[r_ * G3 + HD + j];
            float hgn = hg[r_ * G3 + 2 * HD + j];
            float rr = 1.f / (1.f + __expf(-(xr + hgr)));
            float zz = 1.f / (1.f + __expf(-(xz + hgz)));
            float nn = tanhf(xn + rr * hgn);
            float hold = h_s[r_ * HP + j];
            float hn = (1.f - zz) * nn + zz * hold;
            h_s[r_ * HP + j] = hn;
            g_hcat[((size_t)(rb + r_) * TLEN + t) * H2 + dir * HD + j] = hn;
        }
    }
}

// =====================================================================
// K3: attention score (float4-vectorized xs, padded stride 464)
// smem: xs[32*464] + Wt[460*65] + red[64*32] = 187,184 B
// =====================================================================
#define XP 464
__global__ void __launch_bounds__(256) k_score(const float* __restrict__ X,
        const float* __restrict__ W, const float* __restrict__ b,
        const float* __restrict__ p, float* __restrict__ s)
{
    extern __shared__ float sm[];
    float* xs  = sm;
    float* Wt  = sm + 32 * XP;
    float* red = Wt + H2 * 65;

    const int r0 = blockIdx.x * 32;
    const int tid = threadIdx.x;
    const int jx = tid & 63;
    const int ry = tid >> 6;

    for (int idx = tid; idx < 32 * XP; idx += 256) {
        int r = idx / XP, c = idx - r * XP;
        xs[idx] = (c < H2) ? X[((size_t)r0 + r) * H2 + c] : 0.f;
    }

    float sacc[8] = {};
    for (int j0 = 0; j0 < H2; j0 += 64) {
        __syncthreads();
        for (int idx = tid; idx < H2 * 64; idx += 256) {
            int i  = idx >> 6;
            int jj = idx & 63;
            int j = j0 + jj;
            Wt[i * 65 + jj] = (j < H2) ? W[(size_t)i * H2 + j] : 0.f;
        }
        __syncthreads();
        int j = j0 + jx;
        if (j < H2) {
            float facc[8] = {};
            for (int i = 0; i < H2; i += 4) {
                float w0 = Wt[(i + 0) * 65 + jx];
                float w1 = Wt[(i + 1) * 65 + jx];
                float w2 = Wt[(i + 2) * 65 + jx];
                float w3 = Wt[(i + 3) * 65 + jx];
                #pragma unroll
                for (int r = 0; r < 8; r++) {
                    float4 x4 = *(const float4*)(xs + (ry * 8 + r) * XP + i);
                    facc[r] = fmaf(w0, x4.x, fmaf(w1, x4.y, fmaf(w2, x4.z, fmaf(w3, x4.w, facc[r]))));
                }
            }
            float pj = p[j], bj = b[j];
            #pragma unroll
            for (int r = 0; r < 8; r++)
                sacc[r] += pj * tanhf(facc[r] + bj);
        }
    }
    __syncthreads();
    #pragma unroll
    for (int r = 0; r < 8; r++)
        red[jx * 32 + ry * 8 + r] = sacc[r];
    __syncthreads();
    if (tid < 32) {
        float v = 0.f;
        for (int q = 0; q < 64; q++) v += red[q * 32 + tid];
        s[r0 + tid] = v;
    }
}

// =====================================================================
// K4: softmax + weighted sum
// =====================================================================
__global__ void k_attnsum(const float* __restrict__ s, const float* __restrict__ X,
                          float* __restrict__ V, int L)
{
    __shared__ float sv[64];
    __shared__ float alpha[64];
    const int b = blockIdx.x;
    const int tid = threadIdx.x;
    if (tid < L) sv[tid] = s[b * L + tid];
    __syncthreads();
    float m = -1e30f;
    for (int l = 0; l < L; l++) m = fmaxf(m, sv[l]);
    float den = 0.f;
    for (int l = 0; l < L; l++) den += __expf(sv[l] - m);
    if (tid < L) alpha[tid] = __expf(sv[tid] - m) / den;
    __syncthreads();
    for (int j = tid; j < H2; j += blockDim.x) {
        float acc = 0.f;
        for (int l = 0; l < L; l++)
            acc += alpha[l] * X[((size_t)b * L + l) * H2 + j];
        V[(size_t)b * H2 + j] = acc;
    }
}

// =====================================================================
// K5: FC + scatter
// =====================================================================
__global__ void k_fc_scatter(const float* __restrict__ fcW, const float* __restrict__ fcb,
                             const int* __restrict__ pairs, float* __restrict__ out)
{
    __shared__ float sv[H2];
    const int r = blockIdx.x;
    const int tid = threadIdx.x;
    for (int j = tid; j < H2; j += blockDim.x) sv[j] = g_sv[(size_t)r * H2 + j];
    __syncthreads();
    if (tid < OUTD) {
        float acc = fcb[tid];
        for (int j = 0; j < H2; j++) acc += sv[j] * fcW[(size_t)tid * H2 + j];
        int p0 = pairs[r * 3], p1 = pairs[r * 3 + 1], p2 = pairs[r * 3 + 2];
        out[((size_t)(p0 * 64 + p1 * 8 + p2)) * OUTD + tid] = acc;
    }
}

__global__ void k_zero(float* __restrict__ out, int n)
{
    int i = blockIdx.x * blockDim.x + threadIdx.x;
    if (i < n) out[i] = 0.f;
}

// =====================================================================
extern "C" void kernel_launch(void* const* d_in, const int* in_sizes, int n_in,
                              void* d_out, int out_size)
{
    const float* bag   = (const float*)d_in[0];
    const float* Wihf  = (const float*)d_in[1];
    const float* Whhf  = (const float*)d_in[2];
    const float* bihf  = (const float*)d_in[3];
    const float* bhhf  = (const float*)d_in[4];
    const float* Wihr  = (const float*)d_in[5];
    const float* Whhr  = (const float*)d_in[6];
    const float* bihr  = (const float*)d_in[7];
    const float* bhhr  = (const float*)d_in[8];
    const float* Wword = (const float*)d_in[9];
    const float* bword = (const float*)d_in[10];
    const float* pword = (const float*)d_in[11];
    const float* Wsent = (const float*)d_in[12];
    const float* bsent = (const float*)d_in[13];
    const float* psent = (const float*)d_in[14];
    const float* fcW   = (const float*)d_in[15];
    const float* fcb   = (const float*)d_in[16];
    const int*   pairs = (const int*)d_in[17];
    float* out = (float*)d_out;

    void *p_hcat, *p_sw, *p_wv, *p_ss, *p_sv;
    cudaGetSymbolAddress(&p_hcat, g_hcat);
    cudaGetSymbolAddress(&p_sw,   g_sw);
    cudaGetSymbolAddress(&p_wv,   g_wv);
    cudaGetSymbolAddress(&p_ss,   g_ss);
    cudaGetSymbolAddress(&p_sv,   g_sv);

    const size_t smem_gru   = (size_t)(32 * HP + 64 * HP + 32 * G3) * sizeof(float);  // 178,944
    const size_t smem_score = (size_t)(32 * XP + H2 * 65 + 64 * 32) * sizeof(float);  // 187,184
    cudaFuncSetAttribute(k_gru,   cudaFuncAttributeMaxDynamicSharedMemorySize, (int)smem_gru);
    cudaFuncSetAttribute(k_score, cudaFuncAttributeMaxDynamicSharedMemorySize, (int)smem_score);

    // 1) zero output (poisoned by harness)
    k_zero<<<(out_size + 255) / 256, 256>>>(out, out_size);

    // 2) pack operands in mma fragment order (split bf16)
    k_pack_a<<<MATOMS, 256>>>(bag);
    k_pack_b<<<2 * NATOMS, 128>>>(Wihf, Wihr);

    // 3) input projection on tensor pipe (HMMA), both dirs
    dim3 gmma(6, ROWSALL / 128, 2);
    k_mma_proj<<<gmma, 256>>>(bihf, bihr);

    // 4) bidirectional GRU
    k_gru<<<256, 256, smem_gru>>>(Whhf, bhhf, Whhr, bhhr);

    // 5) word attention
    k_score<<<ROWSALL / 32, 256, smem_score>>>((const float*)p_hcat, Wword, bword, pword, (float*)p_sw);
    k_attnsum<<<BALL, 256>>>((const float*)p_sw, (const float*)p_hcat, (float*)p_wv, TLEN);

    // 6) sentence attention
    k_score<<<BALL / 32, 256, smem_score>>>((const float*)p_wv, Wsent, bsent, psent, (float*)p_ss);
    k_attnsum<<<NBAGS, 256>>>((const float*)p_ss, (const float*)p_wv, (float*)p_sv, MSENT);

    // 7) FC + scatter
    k_fc_scatter<<<NBAGS, 64>>>(fcW, fcb, pairs, out);
}

// round 14
// speedup vs baseline: 3.1325x; 2.4351x over previous
#include <cuda_runtime.h>
#include <cuda_bf16.h>
#include <cstdint>

// Problem dims
#define NBAGS 512
#define MSENT 8
#define TLEN  64
#define IND   360
#define HD    230
#define G3    690
#define H2    460
#define OUTD  53
#define BALL  4096
#define ROWSALL 262144

// proj GEMM atoms (K 360->384, N 690->768)
#define KATOMS 24
#define MATOMS (ROWSALL/16)
#define NATOMS 96
// score GEMM atoms (K 460->480, N 460->512)
#define SK 30
// gru GEMM atoms (K 230->240, N 690->704)
#define GK 15
#define GN 88

// ---------------- scratch (static device globals) ----------------
__device__ float g_xg_f[(size_t)ROWSALL * G3];
__device__ float g_xg_r[(size_t)ROWSALL * G3];
__device__ float g_hcat[(size_t)ROWSALL * H2];
// proj fragments
__device__ __nv_bfloat16 g_Ahi[(size_t)MATOMS * KATOMS * 256];
__device__ __nv_bfloat16 g_Alo[(size_t)MATOMS * KATOMS * 256];
__device__ __nv_bfloat16 g_Bhi[(size_t)2 * NATOMS * KATOMS * 128];
__device__ __nv_bfloat16 g_Blo[(size_t)2 * NATOMS * KATOMS * 128];
// gru W fragments
__device__ __nv_bfloat16 g_Wghi[(size_t)2 * GN * GK * 128];
__device__ __nv_bfloat16 g_Wglo[(size_t)2 * GN * GK * 128];
// word score X fragments (262144 rows)
__device__ __nv_bfloat16 g_Xwhi[(size_t)(ROWSALL/16) * SK * 256];
__device__ __nv_bfloat16 g_Xwlo[(size_t)(ROWSALL/16) * SK * 256];
// sentence score X fragments (4096 rows)
__device__ __nv_bfloat16 g_Xshi[(size_t)(BALL/16) * SK * 256];
__device__ __nv_bfloat16 g_Xslo[(size_t)(BALL/16) * SK * 256];
// score W fragments (word + sent)
__device__ __nv_bfloat16 g_Bw1hi[(size_t)64 * SK * 128];
__device__ __nv_bfloat16 g_Bw1lo[(size_t)64 * SK * 128];
__device__ __nv_bfloat16 g_Bw2hi[(size_t)64 * SK * 128];
__device__ __nv_bfloat16 g_Bw2lo[(size_t)64 * SK * 128];
__device__ float g_sw[ROWSALL];
__device__ float g_wv[(size_t)BALL * H2];
__device__ float g_ss[BALL];
__device__ float g_sv[(size_t)NBAGS * H2];

// ---------------- helpers ----------------
__device__ __forceinline__ unsigned pack_split(float x, float y, unsigned& lo)
{
    __nv_bfloat16 hx = __float2bfloat16(x);
    __nv_bfloat16 hy = __float2bfloat16(y);
    __nv_bfloat16 lx = __float2bfloat16(x - __bfloat162float(hx));
    __nv_bfloat16 ly = __float2bfloat16(y - __bfloat162float(hy));
    __nv_bfloat162 ph; ph.x = hx; ph.y = hy;
    __nv_bfloat162 pl; pl.x = lx; pl.y = ly;
    lo = *(unsigned*)&pl;
    return *(unsigned*)&ph;
}

__device__ __forceinline__ float tanh_fast(float x)
{
    float e = __expf(2.f * x);
    return 1.f - __fdividef(2.f, e + 1.f);
}

#define MMA16816(c, a, b) \
    asm volatile("mma.sync.aligned.m16n8k16.row.col.f32.bf16.bf16.f32 " \
        "{%0,%1,%2,%3}, {%4,%5,%6,%7}, {%8,%9}, {%0,%1,%2,%3};" \
        : "+f"((c)[0]), "+f"((c)[1]), "+f"((c)[2]), "+f"((c)[3]) \
        : "r"((a).x), "r"((a).y), "r"((a).z), "r"((a).w), "r"((b).x), "r"((b).y))

// =====================================================================
// pack A (bag) into mma fragment order, split bf16 hi/lo (proj, K=384)
// =====================================================================
__global__ void __launch_bounds__(256) k_pack_a(const float* __restrict__ bag)
{
    const int mi  = blockIdx.x;
    const int wid = threadIdx.x >> 5, lane = threadIdx.x & 31;
    const int gid = lane >> 2, tig = lane & 3;
    const size_t r0 = (size_t)mi * 16 + gid;
    const size_t r1 = r0 + 8;
    for (int ki = wid; ki < KATOMS; ki += 8) {
        const int kb = ki * 16 + tig * 2;
        float2 v0 = (kb     < IND) ? *(const float2*)(bag + r0 * IND + kb)     : make_float2(0.f, 0.f);
        float2 v1 = (kb     < IND) ? *(const float2*)(bag + r1 * IND + kb)     : make_float2(0.f, 0.f);
        float2 v2 = (kb + 8 < IND) ? *(const float2*)(bag + r0 * IND + kb + 8) : make_float2(0.f, 0.f);
        float2 v3 = (kb + 8 < IND) ? *(const float2*)(bag + r1 * IND + kb + 8) : make_float2(0.f, 0.f);
        uint4 hi, lo;
        hi.x = pack_split(v0.x, v0.y, lo.x);
        hi.y = pack_split(v1.x, v1.y, lo.y);
        hi.z = pack_split(v2.x, v2.y, lo.z);
        hi.w = pack_split(v3.x, v3.y, lo.w);
        size_t off = ((size_t)mi * KATOMS + ki) * 256 + lane * 8;
        *(uint4*)(g_Ahi + off) = hi;
        *(uint4*)(g_Alo + off) = lo;
    }
}

// =====================================================================
// pack W_ih (both dirs) into B fragment order (proj)
// =====================================================================
__global__ void __launch_bounds__(128) k_pack_b(const float* __restrict__ Wf, const float* __restrict__ Wr)
{
    const int b = blockIdx.x;
    const int dir = b / NATOMS, ni = b - dir * NATOMS;
    const float* W = dir ? Wr : Wf;
    const int wid = threadIdx.x >> 5, lane = threadIdx.x & 31;
    const int gid = lane >> 2, tig = lane & 3;
    const int n = ni * 8 + gid;
    const bool nok = (n < G3);
    for (int ki = wid; ki < KATOMS; ki += 4) {
        const int kb = ki * 16 + tig * 2;
        float2 v0 = (nok && kb     < IND) ? *(const float2*)(W + (size_t)n * IND + kb)     : make_float2(0.f, 0.f);
        float2 v1 = (nok && kb + 8 < IND) ? *(const float2*)(W + (size_t)n * IND + kb + 8) : make_float2(0.f, 0.f);
        uint2 hi, lo;
        hi.x = pack_split(v0.x, v0.y, lo.x);
        hi.y = pack_split(v1.x, v1.y, lo.y);
        size_t off = ((size_t)b * KATOMS + ki) * 128 + lane * 4;
        *(uint2*)(g_Bhi + off) = hi;
        *(uint2*)(g_Blo + off) = lo;
    }
}

// =====================================================================
// proj GEMM via mma.sync (verified in R9)
// =====================================================================
__global__ void __launch_bounds__(256) k_mma_proj(const float* __restrict__ bf_, const float* __restrict__ br_)
{
    const int tid = threadIdx.x, wid = tid >> 5, lane = tid & 31;
    const int wm = wid >> 2, wn = wid & 3;
    const int m0 = blockIdx.y * 128;
    const int n0 = blockIdx.x * 128;
    const int dir = blockIdx.z;

    const __nv_bfloat16* Bh = g_Bhi + (size_t)dir * NATOMS * KATOMS * 128;
    const __nv_bfloat16* Bl = g_Blo + (size_t)dir * NATOMS * KATOMS * 128;

    const int miG0 = (m0 >> 4) + wm * 4;
    const int niG0 = (n0 >> 3) + wn * 4;

    float acc[4][4][4] = {};

    for (int ki = 0; ki < KATOMS; ki++) {
        uint4 ah[4], al[4];
        uint2 bh[4], bl[4];
        #pragma unroll
        for (int mi = 0; mi < 4; mi++) {
            size_t off = ((size_t)(miG0 + mi) * KATOMS + ki) * 256 + lane * 8;
            ah[mi] = *(const uint4*)(g_Ahi + off);
            al[mi] = *(const uint4*)(g_Alo + off);
        }
        #pragma unroll
        for (int ni = 0; ni < 4; ni++) {
            size_t off = ((size_t)(niG0 + ni) * KATOMS + ki) * 128 + lane * 4;
            bh[ni] = *(const uint2*)(Bh + off);
            bl[ni] = *(const uint2*)(Bl + off);
        }
        #pragma unroll
        for (int mi = 0; mi < 4; mi++)
            #pragma unroll
            for (int ni = 0; ni < 4; ni++) {
                MMA16816(acc[mi][ni], ah[mi], bh[ni]);
                MMA16816(acc[mi][ni], ah[mi], bl[ni]);
                MMA16816(acc[mi][ni], al[mi], bh[ni]);
            }
    }

    const float* bias = dir ? br_ : bf_;
    float* C = dir ? g_xg_r : g_xg_f;
    const int gid = lane >> 2, tig = lane & 3;
    #pragma unroll
    for (int mi = 0; mi < 4; mi++) {
        const size_t r0 = (size_t)m0 + wm * 64 + mi * 16 + gid;
        const size_t r1 = r0 + 8;
        #pragma unroll
        for (int ni = 0; ni < 4; ni++) {
            const int g = n0 + wn * 32 + ni * 8 + tig * 2;
            if (g < G3) {
                float2 bv = *(const float2*)(bias + g);
                float2 o0 = make_float2(acc[mi][ni][0] + bv.x, acc[mi][ni][1] + bv.y);
                float2 o1 = make_float2(acc[mi][ni][2] + bv.x, acc[mi][ni][3] + bv.y);
                *(float2*)(C + r0 * G3 + g) = o0;
                *(float2*)(C + r1 * G3 + g) = o1;
            }
        }
    }
}

// =====================================================================
// pack W_hh (both dirs) into B fragment order (gru: N=704, K=240)
// element source: Whh[n][k], guards n<690, k<230
// =====================================================================
__global__ void __launch_bounds__(128) k_pack_wgru(const float* __restrict__ Wf, const float* __restrict__ Wr)
{
    const int b = blockIdx.x;            // 0..2*GN-1
    const int dir = b / GN, na = b - dir * GN;
    const float* W = dir ? Wr : Wf;
    const int wid = threadIdx.x >> 5, lane = threadIdx.x & 31;
    const int gid = lane >> 2, tig = lane & 3;
    const int n = na * 8 + gid;
    for (int ki = wid; ki < GK; ki += 4) {
        const int kb = ki * 16 + tig * 2;
        float e0 = (n < G3 && kb     < HD) ? W[(size_t)n * HD + kb]     : 0.f;
        float e1 = (n < G3 && kb + 1 < HD) ? W[(size_t)n * HD + kb + 1] : 0.f;
        float e2 = (n < G3 && kb + 8 < HD) ? W[(size_t)n * HD + kb + 8] : 0.f;
        float e3 = (n < G3 && kb + 9 < HD) ? W[(size_t)n * HD + kb + 9] : 0.f;
        uint2 hi, lo;
        hi.x = pack_split(e0, e1, lo.x);
        hi.y = pack_split(e2, e3, lo.y);
        size_t off = ((size_t)b * GK + ki) * 128 + lane * 4;
        *(uint2*)(g_Wghi + off) = hi;
        *(uint2*)(g_Wglo + off) = lo;
    }
}

// =====================================================================
// GRU via mma.sync. One CTA = 32 rows, one dir, full T loop.
// Per step: h (smem fp32) -> split-bf16 A fragments (smem) -> 8 warps
// x 11 n-atoms x 15 k-atoms x 3 split MMAs -> hg smem -> gates.
// smem: h_s 32x240 f32 | aHi/aLo 3840 u32 each | hg 32x690 f32 | bias 690
// =====================================================================
__global__ void __launch_bounds__(256) k_gru_mma(const float* __restrict__ bhhf,
                                                 const float* __restrict__ bhhr)
{
    extern __shared__ float sm[];
    float*    h_s = sm;                                  // 7680 floats
    uint32_t* aHi = (uint32_t*)(sm + 32 * 240);          // 3840 u32
    uint32_t* aLo = aHi + 3840;                          // 3840 u32
    float*    hg  = (float*)(aLo + 3840);                // 32*690 floats
    float*    bb  = hg + 32 * 690;                       // 690 floats

    const int bx  = blockIdx.x;
    const int dir = bx >> 7;
    const int rb  = (bx & 127) * 32;
    const float* bhh = dir ? bhhr : bhhf;
    const float* xg  = dir ? g_xg_r : g_xg_f;
    const __nv_bfloat16* WH = g_Wghi + (size_t)dir * GN * GK * 128;
    const __nv_bfloat16* WL = g_Wglo + (size_t)dir * GN * GK * 128;

    const int tid = threadIdx.x, wid = tid >> 5, lane = tid & 31;
    const int gid = lane >> 2, tig = lane & 3;

    for (int i = tid; i < 32 * 240; i += 256) h_s[i] = 0.f;
    for (int i = tid; i < G3; i += 256) bb[i] = bhh[i];
    __syncthreads();

    for (int ti = 0; ti < TLEN; ti++) {
        const int t = dir ? (TLEN - 1 - ti) : ti;

        // build A fragments from h_s (split bf16)
        for (int u = tid; u < 3840; u += 256) {
            int mk = u >> 7;                    // 0..29 = mi*GK+ki
            int mi = mk / GK, ki = mk - mi * GK;
            int l = (u >> 2) & 31, r = u & 3;
            int row = mi * 16 + (l >> 2) + ((r & 1) ? 8 : 0);
            int k   = ki * 16 + (l & 3) * 2 + ((r & 2) ? 8 : 0);
            float x = h_s[row * 240 + k];
            float y = h_s[row * 240 + k + 1];
            unsigned lo; unsigned hi = pack_split(x, y, lo);
            aHi[u] = hi; aLo[u] = lo;
        }
        __syncthreads();

        // warp wid computes n-atoms wid*11 .. wid*11+10
        {
            float acc[2][11][4];
            #pragma unroll
            for (int mi = 0; mi < 2; mi++)
                #pragma unroll
                for (int ni = 0; ni < 11; ni++)
                    #pragma unroll
                    for (int r = 0; r < 4; r++) acc[mi][ni][r] = 0.f;

            for (int ki = 0; ki < GK; ki++) {
                uint4 ah[2], al[2];
                #pragma unroll
                for (int mi = 0; mi < 2; mi++) {
                    ah[mi] = *(uint4*)(aHi + (mi * GK + ki) * 128 + lane * 4);
                    al[mi] = *(uint4*)(aLo + (mi * GK + ki) * 128 + lane * 4);
                }
                uint2 bh[11], bl[11];
                #pragma unroll
                for (int ni = 0; ni < 11; ni++) {
                    size_t off = ((size_t)(wid * 11 + ni) * GK + ki) * 128 + lane * 4;
                    bh[ni] = *(const uint2*)(WH + off);
                    bl[ni] = *(const uint2*)(WL + off);
                }
                #pragma unroll
                for (int mi = 0; mi < 2; mi++)
                    #pragma unroll
                    for (int ni = 0; ni < 11; ni++) {
                        MMA16816(acc[mi][ni], ah[mi], bh[ni]);
                        MMA16816(acc[mi][ni], ah[mi], bl[ni]);
                        MMA16816(acc[mi][ni], al[mi], bh[ni]);
                    }
            }

            // store hg (+bias). n even and < 690 => n+1 <= 689 safe.
            #pragma unroll
            for (int mi = 0; mi < 2; mi++) {
                int r0 = mi * 16 + gid, r1 = r0 + 8;
                #pragma unroll
                for (int ni = 0; ni < 11; ni++) {
                    int n = wid * 88 + ni * 8 + tig * 2;
                    if (n < G3) {
                        float b0 = bb[n], b1 = bb[n + 1];
                        hg[r0 * G3 + n]     = acc[mi][ni][0] + b0;
                        hg[r0 * G3 + n + 1] = acc[mi][ni][1] + b1;
                        hg[r1 * G3 + n]     = acc[mi][ni][2] + b0;
                        hg[r1 * G3 + n + 1] = acc[mi][ni][3] + b1;
                    }
                }
            }
        }
        __syncthreads();

        // gates + state update + output
        for (int e = tid; e < 32 * HD; e += 256) {
            int r_ = e / HD, j = e - r_ * HD;
            size_t xb = ((size_t)(rb + r_) * TLEN + t) * G3;
            float xr = xg[xb + j];
            float xz = xg[xb + HD + j];
            float xn = xg[xb + 2 * HD + j];
            float hgr = hg[r_ * G3 + j];
            float hgz = hg[r_ * G3 + HD + j];
            float hgn = hg[r_ * G3 + 2 * HD + j];
            float rr = __fdividef(1.f, 1.f + __expf(-(xr + hgr)));
            float zz = __fdividef(1.f, 1.f + __expf(-(xz + hgz)));
            float nn = tanh_fast(xn + rr * hgn);
            float hold = h_s[r_ * 240 + j];
            float hn = (1.f - zz) * nn + zz * hold;
            h_s[r_ * 240 + j] = hn;
            g_hcat[((size_t)(rb + r_) * TLEN + t) * H2 + dir * HD + j] = hn;
        }
        __syncthreads();
    }
}

// =====================================================================
// pack X rows [R x 460] into A fragment order (score, K=480)
// =====================================================================
__global__ void __launch_bounds__(256) k_pack_x(const float* __restrict__ X,
        __nv_bfloat16* __restrict__ hi_, __nv_bfloat16* __restrict__ lo_)
{
    const int mi  = blockIdx.x;
    const int wid = threadIdx.x >> 5, lane = threadIdx.x & 31;
    const int gid = lane >> 2, tig = lane & 3;
    const size_t r0 = (size_t)mi * 16 + gid;
    const size_t r1 = r0 + 8;
    for (int ki = wid; ki < SK; ki += 8) {
        const int kb = ki * 16 + tig * 2;
        float2 z = make_float2(0.f, 0.f);
        float2 v0 = (kb     < H2) ? *(const float2*)(X + r0 * H2 + kb)     : z;
        float2 v1 = (kb     < H2) ? *(const float2*)(X + r1 * H2 + kb)     : z;
        float2 v2 = (kb + 8 < H2) ? *(const float2*)(X + r0 * H2 + kb + 8) : z;
        float2 v3 = (kb + 8 < H2) ? *(const float2*)(X + r1 * H2 + kb + 8) : z;
        uint4 hi, lo;
        hi.x = pack_split(v0.x, v0.y, lo.x);
        hi.y = pack_split(v1.x, v1.y, lo.y);
        hi.z = pack_split(v2.x, v2.y, lo.z);
        hi.w = pack_split(v3.x, v3.y, lo.w);
        size_t off = ((size_t)mi * SK + ki) * 256 + lane * 8;
        *(uint4*)(hi_ + off) = hi;
        *(uint4*)(lo_ + off) = lo;
    }
}

// =====================================================================
// pack score W [460 x 460] (k-major rows) into B fragment order
// element source: W[k][n] = W[k*460+n]
// =====================================================================
__global__ void __launch_bounds__(128) k_pack_wsc(const float* __restrict__ W,
        __nv_bfloat16* __restrict__ hi_, __nv_bfloat16* __restrict__ lo_)
{
    const int na  = blockIdx.x;          // 0..63
    const int wid = threadIdx.x >> 5, lane = threadIdx.x & 31;
    const int gid = lane >> 2, tig = lane & 3;
    const int n = na * 8 + gid;
    for (int ki = wid; ki < SK; ki += 4) {
        const int kb = ki * 16 + tig * 2;
        float e0 = (n < H2 && kb     < H2) ? W[(size_t)(kb)     * H2 + n] : 0.f;
        float e1 = (n < H2 && kb + 1 < H2) ? W[(size_t)(kb + 1) * H2 + n] : 0.f;
        float e2 = (n < H2 && kb + 8 < H2) ? W[(size_t)(kb + 8) * H2 + n] : 0.f;
        float e3 = (n < H2 && kb + 9 < H2) ? W[(size_t)(kb + 9) * H2 + n] : 0.f;
        uint2 hi, lo;
        hi.x = pack_split(e0, e1, lo.x);
        hi.y = pack_split(e2, e3, lo.y);
        size_t off = ((size_t)na * SK + ki) * 128 + lane * 4;
        *(uint2*)(hi_ + off) = hi;
        *(uint2*)(lo_ + off) = lo;
    }
}

// =====================================================================
// score via mma.sync: s[row] = sum_n p[n]*tanh( (X@W)[row][n] + b[n] )
// CTA = 128 rows; N=512 in 4 passes of 128; K=480. Fused tanh+dot epilogue.
// =====================================================================
__global__ void __launch_bounds__(256) k_score_mma(
        const __nv_bfloat16* __restrict__ Xhi, const __nv_bfloat16* __restrict__ Xlo,
        const __nv_bfloat16* __restrict__ Bh_, const __nv_bfloat16* __restrict__ Bl_,
        const float* __restrict__ b, const float* __restrict__ p,
        float* __restrict__ sout)
{
    __shared__ float p_s[H2], b_s[H2];
    __shared__ float red[4][128];
    const int tid = threadIdx.x, wid = tid >> 5, lane = tid & 31;
    const int wm = wid >> 2, wn = wid & 3;
    const int gid = lane >> 2, tig = lane & 3;
    const int r0 = blockIdx.x * 128;
    for (int i = tid; i < H2; i += 256) { p_s[i] = p[i]; b_s[i] = b[i]; }
    __syncthreads();

    float rs[4][2] = {};
    const int ma0 = blockIdx.x * 8 + wm * 4;

    for (int pass = 0; pass < 4; pass++) {
        float acc[4][4][4] = {};
        for (int ki = 0; ki < SK; ki++) {
            uint4 ah[4], al[4];
            #pragma unroll
            for (int mi = 0; mi < 4; mi++) {
                size_t off = ((size_t)(ma0 + mi) * SK + ki) * 256 + lane * 8;
                ah[mi] = *(const uint4*)(Xhi + off);
                al[mi] = *(const uint4*)(Xlo + off);
            }
            uint2 bh[4], bl[4];
            #pragma unroll
            for (int ni = 0; ni < 4; ni++) {
                size_t off = ((size_t)(pass * 16 + wn * 4 + ni) * SK + ki) * 128 + lane * 4;
                bh[ni] = *(const uint2*)(Bh_ + off);
                bl[ni] = *(const uint2*)(Bl_ + off);
            }
            #pragma unroll
            for (int mi = 0; mi < 4; mi++)
                #pragma unroll
                for (int ni = 0; ni < 4; ni++) {
                    MMA16816(acc[mi][ni], ah[mi], bh[ni]);
                    MMA16816(acc[mi][ni], ah[mi], bl[ni]);
                    MMA16816(acc[mi][ni], al[mi], bh[ni]);
                }
        }
        // fold this pass into per-thread row sums (n even, <460 => n+1 safe)
        #pragma unroll
        for (int mi = 0; mi < 4; mi++)
            #pragma unroll
            for (int ni = 0; ni < 4; ni++) {
                int n = pass * 128 + wn * 32 + ni * 8 + tig * 2;
                if (n < H2) {
                    float p0 = p_s[n], p1 = p_s[n + 1];
                    float b0 = b_s[n], b1 = b_s[n + 1];
                    rs[mi][0] += p0 * tanh_fast(acc[mi][ni][0] + b0)
                               + p1 * tanh_fast(acc[mi][ni][1] + b1);
                    rs[mi][1] += p0 * tanh_fast(acc[mi][ni][2] + b0)
                               + p1 * tanh_fast(acc[mi][ni][3] + b1);
                }
            }
    }

    // reduce over tig (4 lanes), then across wn warps via smem (deterministic)
    #pragma unroll
    for (int mi = 0; mi < 4; mi++)
        #pragma unroll
        for (int h = 0; h < 2; h++) {
            float v = rs[mi][h];
            v += __shfl_xor_sync(0xffffffffu, v, 1);
            v += __shfl_xor_sync(0xffffffffu, v, 2);
            rs[mi][h] = v;
        }
    if (tig == 0) {
        #pragma unroll
        for (int mi = 0; mi < 4; mi++) {
            red[wn][wm * 64 + mi * 16 + gid]     = rs[mi][0];
            red[wn][wm * 64 + mi * 16 + gid + 8] = rs[mi][1];
        }
    }
    __syncthreads();
    if (tid < 128)
        sout[r0 + tid] = red[0][tid] + red[1][tid] + red[2][tid] + red[3][tid];
}

// =====================================================================
// K4: softmax + weighted sum
// =====================================================================
__global__ void k_attnsum(const float* __restrict__ s, const float* __restrict__ X,
                          float* __restrict__ V, int L)
{
    __shared__ float sv[64];
    __shared__ float alpha[64];
    const int b = blockIdx.x;
    const int tid = threadIdx.x;
    if (tid < L) sv[tid] = s[b * L + tid];
    __syncthreads();
    float m = -1e30f;
    for (int l = 0; l < L; l++) m = fmaxf(m, sv[l]);
    float den = 0.f;
    for (int l = 0; l < L; l++) den += __expf(sv[l] - m);
    if (tid < L) alpha[tid] = __expf(sv[tid] - m) / den;
    __syncthreads();
    for (int j = tid; j < H2; j += blockDim.x) {
        float acc = 0.f;
        for (int l = 0; l < L; l++)
            acc += alpha[l] * X[((size_t)b * L + l) * H2 + j];
        V[(size_t)b * H2 + j] = acc;
    }
}

// =====================================================================
// K5: FC + scatter
// =====================================================================
__global__ void k_fc_scatter(const float* __restrict__ fcW, const float* __restrict__ fcb,
                             const int* __restrict__ pairs, float* __restrict__ out)
{
    __shared__ float sv[H2];
    const int r = blockIdx.x;
    const int tid = threadIdx.x;
    for (int j = tid; j < H2; j += blockDim.x) sv[j] = g_sv[(size_t)r * H2 + j];
    __syncthreads();
    if (tid < OUTD) {
        float acc = fcb[tid];
        for (int j = 0; j < H2; j++) acc += sv[j] * fcW[(size_t)tid * H2 + j];
        int p0 = pairs[r * 3], p1 = pairs[r * 3 + 1], p2 = pairs[r * 3 + 2];
        out[((size_t)(p0 * 64 + p1 * 8 + p2)) * OUTD + tid] = acc;
    }
}

__global__ void k_zero(float* __restrict__ out, int n)
{
    int i = blockIdx.x * blockDim.x + threadIdx.x;
    if (i < n) out[i] = 0.f;
}

// =====================================================================
extern "C" void kernel_launch(void* const* d_in, const int* in_sizes, int n_in,
                              void* d_out, int out_size)
{
    const float* bag   = (const float*)d_in[0];
    const float* Wihf  = (const float*)d_in[1];
    const float* Whhf  = (const float*)d_in[2];
    const float* bihf  = (const float*)d_in[3];
    const float* bhhf  = (const float*)d_in[4];
    const float* Wihr  = (const float*)d_in[5];
    const float* Whhr  = (const float*)d_in[6];
    const float* bihr  = (const float*)d_in[7];
    const float* bhhr  = (const float*)d_in[8];
    const float* Wword = (const float*)d_in[9];
    const float* bword = (const float*)d_in[10];
    const float* pword = (const float*)d_in[11];
    const float* Wsent = (const float*)d_in[12];
    const float* bsent = (const float*)d_in[13];
    const float* psent = (const float*)d_in[14];
    const float* fcW   = (const float*)d_in[15];
    const float* fcb   = (const float*)d_in[16];
    const int*   pairs = (const int*)d_in[17];
    float* out = (float*)d_out;

    void *p_hcat, *p_sw, *p_wv, *p_ss, *p_sv;
    void *p_xwhi, *p_xwlo, *p_xshi, *p_xslo;
    void *p_bw1hi, *p_bw1lo, *p_bw2hi, *p_bw2lo;
    cudaGetSymbolAddress(&p_hcat,  g_hcat);
    cudaGetSymbolAddress(&p_sw,    g_sw);
    cudaGetSymbolAddress(&p_wv,    g_wv);
    cudaGetSymbolAddress(&p_ss,    g_ss);
    cudaGetSymbolAddress(&p_sv,    g_sv);
    cudaGetSymbolAddress(&p_xwhi,  g_Xwhi);
    cudaGetSymbolAddress(&p_xwlo,  g_Xwlo);
    cudaGetSymbolAddress(&p_xshi,  g_Xshi);
    cudaGetSymbolAddress(&p_xslo,  g_Xslo);
    cudaGetSymbolAddress(&p_bw1hi, g_Bw1hi);
    cudaGetSymbolAddress(&p_bw1lo, g_Bw1lo);
    cudaGetSymbolAddress(&p_bw2hi, g_Bw2hi);
    cudaGetSymbolAddress(&p_bw2lo, g_Bw2lo);

    // gru smem: h_s 7680f + aHi/aLo 7680 u32 + hg 22080f + bias 690f
    const size_t smem_gru = (size_t)(32 * 240 + 3840 + 3840 + 32 * G3 + G3) * 4; // 152,520 B
    cudaFuncSetAttribute(k_gru_mma, cudaFuncAttributeMaxDynamicSharedMemorySize, (int)smem_gru);

    // 1) zero output (poisoned by harness)
    k_zero<<<(out_size + 255) / 256, 256>>>(out, out_size);

    // 2) proj: pack + HMMA GEMM
    k_pack_a<<<MATOMS, 256>>>(bag);
    k_pack_b<<<2 * NATOMS, 128>>>(Wihf, Wihr);
    dim3 gmma(6, ROWSALL / 128, 2);
    k_mma_proj<<<gmma, 256>>>(bihf, bihr);

    // 3) GRU: pack W_hh fragments + recurrent mma kernel
    k_pack_wgru<<<2 * GN, 128>>>(Whhf, Whhr);
    k_gru_mma<<<256, 256, smem_gru>>>(bhhf, bhhr);

    // 4) word attention: pack hcat + W_word, fused score GEMM, softmax-sum
    k_pack_x<<<ROWSALL / 16, 256>>>((const float*)p_hcat, (__nv_bfloat16*)p_xwhi, (__nv_bfloat16*)p_xwlo);
    k_pack_wsc<<<64, 128>>>(Wword, (__nv_bfloat16*)p_bw1hi, (__nv_bfloat16*)p_bw1lo);
    k_score_mma<<<ROWSALL / 128, 256>>>(
        (const __nv_bfloat16*)p_xwhi, (const __nv_bfloat16*)p_xwlo,
        (const __nv_bfloat16*)p_bw1hi, (const __nv_bfloat16*)p_bw1lo,
        bword, pword, (float*)p_sw);
    k_attnsum<<<BALL, 256>>>((const float*)p_sw, (const float*)p_hcat, (float*)p_wv, TLEN);

    // 5) sentence attention
    k_pack_x<<<BALL / 16, 256>>>((const float*)p_wv, (__nv_bfloat16*)p_xshi, (__nv_bfloat16*)p_xslo);
    k_pack_wsc<<<64, 128>>>(Wsent, (__nv_bfloat16*)p_bw2hi, (__nv_bfloat16*)p_bw2lo);
    k_score_mma<<<BALL / 128, 256>>>(
        (const __nv_bfloat16*)p_xshi, (const __nv_bfloat16*)p_xslo,
        (const __nv_bfloat16*)p_bw2hi, (const __nv_bfloat16*)p_bw2lo,
        bsent, psent, (float*)p_ss);
    k_attnsum<<<NBAGS, 256>>>((const float*)p_ss, (const float*)p_wv, (float*)p_sv, MSENT);

    // 6) FC + scatter
    k_fc_scatter<<<NBAGS, 64>>>(fcW, fcb, pairs, out);
}